// round 2
// baseline (speedup 1.0000x reference)
#include <cuda_runtime.h>
#include <math.h>

// Problem constants (fixed by the dataset)
#define NN 50000
#define EE 320000
#define FIN 128
#define NH 33
#define NC 16
#define HC 528   // NH*NC

// ---------------- device scratch (no allocation allowed) ----------------
__device__ __align__(16) float g_h[(size_t)NN * HC]; // x @ W, [N,H,C] (~105.6 MB)
__device__ float g_asrc[NN * NH];          // per-node src logits
__device__ float g_adst[NN * NH];          // per-node dst logits
__device__ int   g_rowoff[NN + 1];         // CSR row offsets by dst
__device__ int   g_cursor[NN];             // fill cursors
__device__ int   g_deg[NN];                // in-degrees (excl self loop)
__device__ int   g_csrc[EE];               // CSR: src node per edge

__device__ __forceinline__ int clamp_idx(int v) {
    return ((unsigned)v >= (unsigned)NN) ? 0 : v;
}

// ---------------- GEMM: h = x[N,128] @ W[128,528] ----------------
// BM=64, BN=64, BK=32, 256 threads, 4x4 register microtile.
__global__ void gemm_kernel(const float* __restrict__ X, const float* __restrict__ W) {
    __shared__ float xs[32][68];  // transposed: xs[k][m], padded
    __shared__ float ws[32][64];  // ws[k][n]

    const int bm = blockIdx.y * 64;
    const int bn = blockIdx.x * 64;
    const int tid = threadIdx.x;
    const int tx = tid & 15, ty = tid >> 4;

    float acc[4][4];
#pragma unroll
    for (int i = 0; i < 4; i++)
#pragma unroll
        for (int j = 0; j < 4; j++) acc[i][j] = 0.f;

    for (int kk = 0; kk < FIN; kk += 32) {
        // load X tile: 64 rows x 32 k -> 512 float4 / 256 thr = 2 each
#pragma unroll
        for (int it = 0; it < 2; it++) {
            int i = tid + it * 256;          // i in [0,512): r = i/8, k4 = i%8
            int r = i >> 3, k4 = i & 7;
            float4 v = make_float4(0.f, 0.f, 0.f, 0.f);
            int row = bm + r;
            if (row < NN)
                v = *reinterpret_cast<const float4*>(X + (size_t)row * FIN + kk + k4 * 4);
            xs[k4 * 4 + 0][r] = v.x;
            xs[k4 * 4 + 1][r] = v.y;
            xs[k4 * 4 + 2][r] = v.z;
            xs[k4 * 4 + 3][r] = v.w;
        }
        // load W tile: 32 k x 64 n -> 512 float4 / 256 thr = 2 each
#pragma unroll
        for (int it = 0; it < 2; it++) {
            int i = tid + it * 256;          // r = i/16 (k), n4 = i%16
            int k = i >> 4, n4 = i & 15;
            int col = bn + n4 * 4;
            float4 v = make_float4(0.f, 0.f, 0.f, 0.f);
            if (col < HC)
                v = *reinterpret_cast<const float4*>(W + (size_t)(kk + k) * HC + col);
            *reinterpret_cast<float4*>(&ws[k][n4 * 4]) = v;
        }
        __syncthreads();

#pragma unroll
        for (int k = 0; k < 32; k++) {
            float4 a = *reinterpret_cast<const float4*>(&xs[k][ty * 4]);
            float4 b = *reinterpret_cast<const float4*>(&ws[k][tx * 4]);
            float av[4] = {a.x, a.y, a.z, a.w};
            float bv[4] = {b.x, b.y, b.z, b.w};
#pragma unroll
            for (int i = 0; i < 4; i++)
#pragma unroll
                for (int j = 0; j < 4; j++) acc[i][j] = fmaf(av[i], bv[j], acc[i][j]);
        }
        __syncthreads();
    }

#pragma unroll
    for (int i = 0; i < 4; i++) {
        int row = bm + ty * 4 + i;
        if (row >= NN) continue;
#pragma unroll
        for (int j = 0; j < 4; j++) {
            int col = bn + tx * 4 + j;
            if (col < HC) g_h[(size_t)row * HC + col] = acc[i][j];
        }
    }
}

// ---------------- attention logits: a_src/a_dst[n,h] = <h[n,h,:], att[h,:]> ----------------
__global__ void att_kernel(const float* __restrict__ att_src, const float* __restrict__ att_dst) {
    int idx = blockIdx.x * blockDim.x + threadIdx.x;
    if (idx >= NN * NH) return;
    int n = idx / NH, h = idx % NH;
    const float* hp = &g_h[(size_t)n * HC + h * NC];
    float s1 = 0.f, s2 = 0.f;
#pragma unroll
    for (int c = 0; c < NC; c++) {
        float v = hp[c];
        s1 = fmaf(v, att_src[h * NC + c], s1);
        s2 = fmaf(v, att_dst[h * NC + c], s2);
    }
    g_asrc[idx] = s1;
    g_adst[idx] = s2;
}

// ---------------- CSR build ----------------
__global__ void zero_kernel() {
    int i = blockIdx.x * blockDim.x + threadIdx.x;
    if (i < NN) g_deg[i] = 0;
}

__global__ void count_kernel(const int* __restrict__ ei) {
    int e = blockIdx.x * blockDim.x + threadIdx.x;
    if (e >= EE) return;
    int d = clamp_idx(ei[EE + e]);
    atomicAdd(&g_deg[d], 1);
}

__global__ void scan_kernel() {
    __shared__ int sums[1024];
    const int t = threadIdx.x;
    const int CH = (NN + 1023) / 1024;  // 49
    int b = t * CH;
    int e = b + CH; if (e > NN) e = NN;
    if (b > NN) b = NN;
    int s = 0;
    for (int i = b; i < e; i++) s += g_deg[i];
    sums[t] = s;
    __syncthreads();
    for (int off = 1; off < 1024; off <<= 1) {
        int v = (t >= off) ? sums[t - off] : 0;
        __syncthreads();
        sums[t] += v;
        __syncthreads();
    }
    int run = sums[t] - s;  // exclusive prefix
    for (int i = b; i < e; i++) {
        g_rowoff[i] = run;
        g_cursor[i] = run;
        run += g_deg[i];
    }
    if (t == 1023) g_rowoff[NN] = run;  // = EE
}

__global__ void fill_kernel(const int* __restrict__ ei) {
    int e = blockIdx.x * blockDim.x + threadIdx.x;
    if (e >= EE) return;
    int s = clamp_idx(ei[e]);
    int d = clamp_idx(ei[EE + e]);
    int pos = atomicAdd(&g_cursor[d], 1);
    if (pos < EE) g_csrc[pos] = s;
}

// ---------------- fused per-dst node kernel (warp per node) ----------------
__device__ __forceinline__ float lrelu(float x) { return x > 0.f ? x : 0.2f * x; }

__device__ __forceinline__ void accum16(float acc[16], const float* __restrict__ base, float w) {
    const float4* p = reinterpret_cast<const float4*>(base);
    float4 v0 = p[0], v1 = p[1], v2 = p[2], v3 = p[3];
    acc[0]  = fmaf(w, v0.x, acc[0]);  acc[1]  = fmaf(w, v0.y, acc[1]);
    acc[2]  = fmaf(w, v0.z, acc[2]);  acc[3]  = fmaf(w, v0.w, acc[3]);
    acc[4]  = fmaf(w, v1.x, acc[4]);  acc[5]  = fmaf(w, v1.y, acc[5]);
    acc[6]  = fmaf(w, v1.z, acc[6]);  acc[7]  = fmaf(w, v1.w, acc[7]);
    acc[8]  = fmaf(w, v2.x, acc[8]);  acc[9]  = fmaf(w, v2.y, acc[9]);
    acc[10] = fmaf(w, v2.z, acc[10]); acc[11] = fmaf(w, v2.w, acc[11]);
    acc[12] = fmaf(w, v3.x, acc[12]); acc[13] = fmaf(w, v3.y, acc[13]);
    acc[14] = fmaf(w, v3.z, acc[14]); acc[15] = fmaf(w, v3.w, acc[15]);
}

__global__ void node_kernel(const float* __restrict__ bias, float* __restrict__ out) {
    int gw = (blockIdx.x * blockDim.x + threadIdx.x) >> 5;
    if (gw >= NN) return;
    const int n = gw;
    const int lane = threadIdx.x & 31;
    const bool l0 = (lane == 0);

    const int beg = g_rowoff[n];
    const int end = g_rowoff[n + 1];

    // lane owns head = lane (0..31); lane 0 additionally owns head 32
    const float ad0 = g_adst[n * NH + lane];
    const float as0 = g_asrc[n * NH + lane];
    float ad1 = 0.f, as1 = 0.f;
    if (l0) { ad1 = g_adst[n * NH + 32]; as1 = g_asrc[n * NH + 32]; }

    // -------- pass 1: per-head max over {self} U edges --------
    float m0 = lrelu(as0 + ad0);
    float m1 = l0 ? lrelu(as1 + ad1) : -1e30f;
    for (int i = beg; i < end; i++) {
        int s = g_csrc[i];
        float e0 = lrelu(g_asrc[s * NH + lane] + ad0);
        m0 = fmaxf(m0, e0);
        if (l0) {
            float e1 = lrelu(g_asrc[s * NH + 32] + ad1);
            m1 = fmaxf(m1, e1);
        }
    }

    // -------- pass 2: denom --------
    float d0 = __expf(lrelu(as0 + ad0) - m0);
    float d1 = l0 ? __expf(lrelu(as1 + ad1) - m1) : 0.f;
    for (int i = beg; i < end; i++) {
        int s = g_csrc[i];
        float e0 = lrelu(g_asrc[s * NH + lane] + ad0);
        d0 += __expf(e0 - m0);
        if (l0) {
            float e1 = lrelu(g_asrc[s * NH + 32] + ad1);
            d1 += __expf(e1 - m1);
        }
    }
    const float inv0 = 1.f / (d0 + 1e-16f);
    const float inv1 = l0 ? 1.f / (d1 + 1e-16f) : 0.f;

    // -------- pass 3: weighted accumulate, head-mean fused --------
    float acc[16];
#pragma unroll
    for (int c = 0; c < 16; c++) acc[c] = 0.f;

    // self loop
    {
        float w0 = __expf(lrelu(as0 + ad0) - m0) * inv0;
        accum16(acc, &g_h[(size_t)n * HC + lane * NC], w0);
        if (l0) {
            float w1 = __expf(lrelu(as1 + ad1) - m1) * inv1;
            accum16(acc, &g_h[(size_t)n * HC + 32 * NC], w1);
        }
    }
    for (int i = beg; i < end; i++) {
        int s = g_csrc[i];
        float e0 = lrelu(g_asrc[s * NH + lane] + ad0);
        float w0 = __expf(e0 - m0) * inv0;
        accum16(acc, &g_h[(size_t)s * HC + lane * NC], w0);
        if (l0) {
            float e1 = lrelu(g_asrc[s * NH + 32] + ad1);
            float w1 = __expf(e1 - m1) * inv1;
            accum16(acc, &g_h[(size_t)s * HC + 32 * NC], w1);
        }
    }

    // -------- warp reduce across heads (sum over all 33) --------
    float res = 0.f;
#pragma unroll
    for (int c = 0; c < 16; c++) {
        float r = acc[c];
        r += __shfl_xor_sync(0xffffffffu, r, 16);
        r += __shfl_xor_sync(0xffffffffu, r, 8);
        r += __shfl_xor_sync(0xffffffffu, r, 4);
        r += __shfl_xor_sync(0xffffffffu, r, 2);
        r += __shfl_xor_sync(0xffffffffu, r, 1);
        if (lane == c) res = r;
    }
    if (lane < 16)
        out[n * NC + lane] = tanhf(res * (1.f / 33.f) + bias[lane]);
}

// ---------------- launch ----------------
extern "C" void kernel_launch(void* const* d_in, const int* in_sizes, int n_in,
                              void* d_out, int out_size) {
    const float* x     = (const float*)d_in[0];
    const int*   ei    = (const int*)d_in[1];   // edge_index materializes as int32 (JAX x64 off)
    const float* W     = (const float*)d_in[2];
    const float* att_s = (const float*)d_in[3];
    const float* att_d = (const float*)d_in[4];
    const float* bias  = (const float*)d_in[5];
    float*       out   = (float*)d_out;

    // CSR build (independent of GEMM; runs first so later kernels see it)
    zero_kernel<<<(NN + 255) / 256, 256>>>();
    count_kernel<<<(EE + 255) / 256, 256>>>(ei);
    scan_kernel<<<1, 1024>>>();
    fill_kernel<<<(EE + 255) / 256, 256>>>(ei);

    // feature transform + logits
    dim3 gg((HC + 63) / 64, (NN + 63) / 64);  // 9 x 782
    gemm_kernel<<<gg, 256>>>(x, W);
    att_kernel<<<(NN * NH + 255) / 256, 256>>>(att_s, att_d);

    // fused softmax-aggregate-mean-tanh, one warp per dst node
    node_kernel<<<(NN * 32 + 255) / 256, 256>>>(bias, out);
}

// round 3
// speedup vs baseline: 1.3194x; 1.3194x over previous
#include <cuda_runtime.h>
#include <math.h>

// Problem constants (fixed by the dataset)
#define NN 50000
#define EE 320000
#define FIN 128
#define NH 33
#define NC 16
#define HC 528   // NH*NC

// ---------------- device scratch (no allocation allowed) ----------------
__device__ __align__(16) float g_h[(size_t)NN * HC]; // x @ W, [N,H,C] (~105.6 MB)
__device__ float g_asrc[NN * NH];          // per-node src logits
__device__ float g_adst[NN * NH];          // per-node dst logits
__device__ int   g_rowoff[NN + 1];         // CSR row offsets by dst
__device__ int   g_cursor[NN];             // fill cursors
__device__ int   g_deg[NN];                // in-degrees (excl self loop)
__device__ int   g_csrc[EE];               // CSR: src node per edge

__device__ __forceinline__ int clamp_idx(int v) {
    return ((unsigned)v >= (unsigned)NN) ? 0 : v;
}

// ---------------- GEMM: h = x[N,128] @ W[128,528], att logits fused in epilogue ------
// BM=128, BN=64, BK=32, 256 threads, 8x4 register microtile.
__global__ void gemm_kernel(const float* __restrict__ X, const float* __restrict__ W,
                            const float* __restrict__ att_src, const float* __restrict__ att_dst) {
    __shared__ float xs[32][132];  // transposed: xs[k][m], row = 528B (16B aligned)
    __shared__ float ws[32][64];   // ws[k][n]

    const int bm = blockIdx.y * 128;
    const int bn = blockIdx.x * 64;
    const int tid = threadIdx.x;
    const int tx = tid & 15, ty = tid >> 4;

    float acc[8][4];
#pragma unroll
    for (int i = 0; i < 8; i++)
#pragma unroll
        for (int j = 0; j < 4; j++) acc[i][j] = 0.f;

    for (int kk = 0; kk < FIN; kk += 32) {
        // load X tile: 128 rows x 32 k -> 1024 float4 / 256 thr = 4 each
#pragma unroll
        for (int it = 0; it < 4; it++) {
            int i = tid + it * 256;          // i in [0,1024): r = i/8, k4 = i%8
            int r = i >> 3, k4 = i & 7;
            float4 v = make_float4(0.f, 0.f, 0.f, 0.f);
            int row = bm + r;
            if (row < NN)
                v = *reinterpret_cast<const float4*>(X + (size_t)row * FIN + kk + k4 * 4);
            xs[k4 * 4 + 0][r] = v.x;
            xs[k4 * 4 + 1][r] = v.y;
            xs[k4 * 4 + 2][r] = v.z;
            xs[k4 * 4 + 3][r] = v.w;
        }
        // load W tile: 32 k x 64 n -> 512 float4 / 256 thr = 2 each
#pragma unroll
        for (int it = 0; it < 2; it++) {
            int i = tid + it * 256;          // k = i/16, n4 = i%16
            int k = i >> 4, n4 = i & 15;
            int col = bn + n4 * 4;
            float4 v = make_float4(0.f, 0.f, 0.f, 0.f);
            if (col < HC)
                v = *reinterpret_cast<const float4*>(W + (size_t)(kk + k) * HC + col);
            *reinterpret_cast<float4*>(&ws[k][n4 * 4]) = v;
        }
        __syncthreads();

#pragma unroll
        for (int k = 0; k < 32; k++) {
            float4 a0 = *reinterpret_cast<const float4*>(&xs[k][ty * 8]);
            float4 a1 = *reinterpret_cast<const float4*>(&xs[k][ty * 8 + 4]);
            float4 b  = *reinterpret_cast<const float4*>(&ws[k][tx * 4]);
            float av[8] = {a0.x, a0.y, a0.z, a0.w, a1.x, a1.y, a1.z, a1.w};
            float bv[4] = {b.x, b.y, b.z, b.w};
#pragma unroll
            for (int i = 0; i < 8; i++)
#pragma unroll
                for (int j = 0; j < 4; j++) acc[i][j] = fmaf(av[i], bv[j], acc[i][j]);
        }
        __syncthreads();
    }

    // ---- epilogue: store h + fused attention logits ----
    // This block's 64 cols = heads [4*bx, 4*bx+3]; 4 lanes (same tx>>2) share one head.
    const int head = 4 * blockIdx.x + (tx >> 2);
    const bool hv = head < NH;
    float asv[4], adv[4];
#pragma unroll
    for (int j = 0; j < 4; j++) { asv[j] = 0.f; adv[j] = 0.f; }
    if (hv) {
        int cofs = head * NC + (tx & 3) * 4;
#pragma unroll
        for (int j = 0; j < 4; j++) {
            asv[j] = att_src[cofs + j];
            adv[j] = att_dst[cofs + j];
        }
    }

#pragma unroll
    for (int i = 0; i < 8; i++) {
        int row = bm + ty * 8 + i;
        // store h
        if (row < NN) {
#pragma unroll
            for (int j = 0; j < 4; j++) {
                int col = bn + tx * 4 + j;
                if (col < HC) g_h[(size_t)row * HC + col] = acc[i][j];
            }
        }
        // per-head partial dots, reduce across the 4-lane group (lanes l^1, l^2)
        float p1 = 0.f, p2 = 0.f;
#pragma unroll
        for (int j = 0; j < 4; j++) {
            p1 = fmaf(acc[i][j], asv[j], p1);
            p2 = fmaf(acc[i][j], adv[j], p2);
        }
        p1 += __shfl_xor_sync(0xffffffffu, p1, 1);
        p1 += __shfl_xor_sync(0xffffffffu, p1, 2);
        p2 += __shfl_xor_sync(0xffffffffu, p2, 1);
        p2 += __shfl_xor_sync(0xffffffffu, p2, 2);
        if ((tx & 3) == 0 && hv && row < NN) {
            g_asrc[row * NH + head] = p1;
            g_adst[row * NH + head] = p2;
        }
    }
}

// ---------------- CSR build ----------------
__global__ void zero_kernel() {
    int i = blockIdx.x * blockDim.x + threadIdx.x;
    if (i < NN) g_deg[i] = 0;
}

__global__ void count_kernel(const int* __restrict__ ei) {
    int e = blockIdx.x * blockDim.x + threadIdx.x;
    if (e >= EE) return;
    int d = clamp_idx(ei[EE + e]);
    atomicAdd(&g_deg[d], 1);
}

__global__ void scan_kernel() {
    __shared__ int sums[1024];
    const int t = threadIdx.x;
    const int CH = (NN + 1023) / 1024;  // 49
    int b = t * CH;
    int e = b + CH; if (e > NN) e = NN;
    if (b > NN) b = NN;
    int s = 0;
    for (int i = b; i < e; i++) s += g_deg[i];
    sums[t] = s;
    __syncthreads();
    for (int off = 1; off < 1024; off <<= 1) {
        int v = (t >= off) ? sums[t - off] : 0;
        __syncthreads();
        sums[t] += v;
        __syncthreads();
    }
    int run = sums[t] - s;  // exclusive prefix
    for (int i = b; i < e; i++) {
        g_rowoff[i] = run;
        g_cursor[i] = run;
        run += g_deg[i];
    }
    if (t == 1023) g_rowoff[NN] = run;  // = EE
}

__global__ void fill_kernel(const int* __restrict__ ei) {
    int e = blockIdx.x * blockDim.x + threadIdx.x;
    if (e >= EE) return;
    int s = clamp_idx(ei[e]);
    int d = clamp_idx(ei[EE + e]);
    int pos = atomicAdd(&g_cursor[d], 1);
    if (pos < EE) g_csrc[pos] = s;
}

// ---------------- fused per-dst node kernel (warp per node, single pass) ----------------
__device__ __forceinline__ float lrelu(float x) { return x > 0.f ? x : 0.2f * x; }

__device__ __forceinline__ void accum16(float acc[16], const float* __restrict__ base, float w) {
    const float4* p = reinterpret_cast<const float4*>(base);
    float4 v0 = p[0], v1 = p[1], v2 = p[2], v3 = p[3];
    acc[0]  = fmaf(w, v0.x, acc[0]);  acc[1]  = fmaf(w, v0.y, acc[1]);
    acc[2]  = fmaf(w, v0.z, acc[2]);  acc[3]  = fmaf(w, v0.w, acc[3]);
    acc[4]  = fmaf(w, v1.x, acc[4]);  acc[5]  = fmaf(w, v1.y, acc[5]);
    acc[6]  = fmaf(w, v1.z, acc[6]);  acc[7]  = fmaf(w, v1.w, acc[7]);
    acc[8]  = fmaf(w, v2.x, acc[8]);  acc[9]  = fmaf(w, v2.y, acc[9]);
    acc[10] = fmaf(w, v2.z, acc[10]); acc[11] = fmaf(w, v2.w, acc[11]);
    acc[12] = fmaf(w, v3.x, acc[12]); acc[13] = fmaf(w, v3.y, acc[13]);
    acc[14] = fmaf(w, v3.z, acc[14]); acc[15] = fmaf(w, v3.w, acc[15]);
}

__global__ void node_kernel(const float* __restrict__ bias, float* __restrict__ out) {
    int gw = (blockIdx.x * blockDim.x + threadIdx.x) >> 5;
    if (gw >= NN) return;
    const int n = gw;
    const int lane = threadIdx.x & 31;
    const bool l0 = (lane == 0);

    const int beg = g_rowoff[n];
    const int end = g_rowoff[n + 1];

    // lane owns head = lane (0..31); lane 0 additionally owns head 32 (separate accumulator)
    const float ad0 = g_adst[n * NH + lane];
    const float as0 = g_asrc[n * NH + lane];
    float ad1 = 0.f, as1 = 0.f;
    if (l0) { ad1 = g_adst[n * NH + 32]; as1 = g_asrc[n * NH + 32]; }

    float acc0[16], acc1[16];
#pragma unroll
    for (int c = 0; c < 16; c++) { acc0[c] = 0.f; acc1[c] = 0.f; }

    // self loop (logits are small; no max-subtraction needed, exp stays in range)
    float den0 = __expf(lrelu(as0 + ad0));
    accum16(acc0, &g_h[(size_t)n * HC + lane * NC], den0);
    float den1 = 0.f;
    if (l0) {
        den1 = __expf(lrelu(as1 + ad1));
        accum16(acc1, &g_h[(size_t)n * HC + 32 * NC], den1);
    }

    // single pass over incoming edges: accumulate numerator and denominator together
    for (int i = beg; i < end; i++) {
        int s = g_csrc[i];
        float w0 = __expf(lrelu(g_asrc[s * NH + lane] + ad0));
        den0 += w0;
        accum16(acc0, &g_h[(size_t)s * HC + lane * NC], w0);
        if (l0) {
            float w1 = __expf(lrelu(g_asrc[s * NH + 32] + ad1));
            den1 += w1;
            accum16(acc1, &g_h[(size_t)s * HC + 32 * NC], w1);
        }
    }

    const float inv0 = 1.f / den0;
    const float inv1 = l0 ? (1.f / den1) : 0.f;
#pragma unroll
    for (int c = 0; c < 16; c++) acc0[c] = acc0[c] * inv0 + acc1[c] * inv1;

    // warp reduce across heads (sum over all 33)
    float res = 0.f;
#pragma unroll
    for (int c = 0; c < 16; c++) {
        float r = acc0[c];
        r += __shfl_xor_sync(0xffffffffu, r, 16);
        r += __shfl_xor_sync(0xffffffffu, r, 8);
        r += __shfl_xor_sync(0xffffffffu, r, 4);
        r += __shfl_xor_sync(0xffffffffu, r, 2);
        r += __shfl_xor_sync(0xffffffffu, r, 1);
        if (lane == c) res = r;
    }
    if (lane < 16)
        out[n * NC + lane] = tanhf(res * (1.f / 33.f) + bias[lane]);
}

// ---------------- launch ----------------
extern "C" void kernel_launch(void* const* d_in, const int* in_sizes, int n_in,
                              void* d_out, int out_size) {
    const float* x     = (const float*)d_in[0];
    const int*   ei    = (const int*)d_in[1];   // edge_index materializes as int32 (JAX x64 off)
    const float* W     = (const float*)d_in[2];
    const float* att_s = (const float*)d_in[3];
    const float* att_d = (const float*)d_in[4];
    const float* bias  = (const float*)d_in[5];
    float*       out   = (float*)d_out;

    // CSR build
    zero_kernel<<<(NN + 255) / 256, 256>>>();
    count_kernel<<<(EE + 255) / 256, 256>>>(ei);
    scan_kernel<<<1, 1024>>>();
    fill_kernel<<<(EE + 255) / 256, 256>>>(ei);

    // feature transform + fused attention logits
    dim3 gg((HC + 63) / 64, (NN + 127) / 128);  // 9 x 391
    gemm_kernel<<<gg, 256>>>(x, W, att_s, att_d);

    // fused softmax-aggregate-mean-tanh, one warp per dst node
    node_kernel<<<(NN * 32 + 255) / 256, 256>>>(bias, out);
}

// round 6
// speedup vs baseline: 1.7450x; 1.3226x over previous
#include <cuda_runtime.h>
#include <math.h>
#include <stdint.h>

// Problem constants
#define NN 50000
#define EE 320000
#define FIN 128
#define NH 33
#define NC 16
#define HC 528     // NH*NC
#define NB 640     // padded B columns: 528 h | 33 a_src | 33 a_dst | pad

// GEMM tiling (legacy mma.sync m16n8k8 tf32)
#define BM 64
#define BN 128
#define MTILES ((NN + BM - 1) / BM)   // 782
#define NTILES (NB / BN)              // 5

// fragment-packed smem indices (floats); padded slot strides (no overlap):
//   A slot = 132 floats (128 data + 4 pad), 16B-aligned stride for LDS.128
//   B slot = 66 floats (64 data + 2 pad)
#define A_IDX(mt, ks, lane, reg) (((mt)*16 + (ks))*132 + (lane)*4 + (reg))
#define B_IDX(nt, ks, lane, reg) (((nt)*16 + (ks))*66 + (lane)*2 + (reg))
#define A_FLOATS (64*132)             // 8448
#define B_FLOATS (256*66)             // 16896
#define SMEM_GEMM ((A_FLOATS + B_FLOATS) * 4)  // 101376 bytes

// ---------------- device scratch ----------------
__device__ __align__(16) float g_h[(size_t)NN * HC];
__device__ float g_asrc[NN * NH];
__device__ float g_adst[NN * NH];
__device__ __align__(16) float g_b[NB * FIN];  // fused B matrix, [640][128] n-major
__device__ int g_rowoff[NN + 1];
__device__ int g_cursor[NN];
__device__ int g_deg[NN];
__device__ int g_csrc[EE];

__device__ __forceinline__ int clamp_idx(int v) {
    return ((unsigned)v >= (unsigned)NN) ? 0 : v;
}

__device__ __forceinline__ float tf32r(float f) {
    uint32_t o;
    asm("cvt.rna.tf32.f32 %0, %1;" : "=r"(o) : "f"(f));
    return __uint_as_float(o);
}

// ---------------- B prep: B = [W^T | (W@att_src per head)^T | (W@att_dst)^T | 0] ----------------
__global__ void bprep_kernel(const float* __restrict__ W,
                             const float* __restrict__ attS, const float* __restrict__ attD) {
    int i = blockIdx.x * blockDim.x + threadIdx.x;   // i = k*640 + n
    if (i >= NB * FIN) return;
    int k = i / NB, n = i % NB;
    float v = 0.f;
    if (n < HC) {
        v = W[k * HC + n];
    } else if (n < HC + NH) {
        int h = n - HC;
        const float* wp = &W[k * HC + h * NC];
        const float* ap = &attS[h * NC];
#pragma unroll
        for (int c = 0; c < NC; c++) v = fmaf(wp[c], ap[c], v);
    } else if (n < HC + 2 * NH) {
        int h = n - HC - NH;
        const float* wp = &W[k * HC + h * NC];
        const float* ap = &attD[h * NC];
#pragma unroll
        for (int c = 0; c < NC; c++) v = fmaf(wp[c], ap[c], v);
    }
    g_b[(size_t)n * FIN + k] = tf32r(v);
}

// ---------------- tensor-core GEMM (mma.sync tf32), everything fused ----------------
__device__ __forceinline__ void mma8(float d[4], const float4& A, const float2& B) {
    asm volatile(
        "mma.sync.aligned.m16n8k8.row.col.f32.tf32.tf32.f32 "
        "{%0,%1,%2,%3}, {%4,%5,%6,%7}, {%8,%9}, {%0,%1,%2,%3};"
        : "+f"(d[0]), "+f"(d[1]), "+f"(d[2]), "+f"(d[3])
        : "r"(__float_as_uint(A.x)), "r"(__float_as_uint(A.y)),
          "r"(__float_as_uint(A.z)), "r"(__float_as_uint(A.w)),
          "r"(__float_as_uint(B.x)), "r"(__float_as_uint(B.y)));
}

__device__ __forceinline__ void store_one(int row, int col, float v) {
    if (col < HC) g_h[(size_t)row * HC + col] = v;
    else if (col < HC + NH) g_asrc[row * NH + (col - HC)] = v;
    else if (col < HC + 2 * NH) g_adst[row * NH + (col - HC - NH)] = v;
}

__device__ __forceinline__ void store_pair(int row, int col, float v0, float v1) {
    if (row >= NN) return;
    if (col + 1 < HC) {
        *reinterpret_cast<float2*>(&g_h[(size_t)row * HC + col]) = make_float2(v0, v1);
    } else {
        store_one(row, col, v0);
        store_one(row, col + 1, v1);
    }
}

__global__ void __launch_bounds__(256, 2)
gemm_kernel(const float* __restrict__ X) {
    extern __shared__ float sm[];
    float* As = sm;
    float* Bs = sm + A_FLOATS;

    const int tid = threadIdx.x;
    const int wid = tid >> 5;
    const int lane = tid & 31;
    const int bm = blockIdx.y * BM;
    const int bn = blockIdx.x * BN;

    // ---- A copy: 64 rows x 32 float4, fragment-packed ----
    // fragment (m16n8k8 tf32 A): lane = groupID*4 + tid_g; groupID = row&7, tid_g = k&3;
    // reg = (row>=8) + 2*(kwithin8>=4)
#pragma unroll
    for (int it = 0; it < 8; it++) {
        int i = tid + it * 256;
        int r = i >> 5, c4 = i & 31;
        int row = bm + r; if (row >= NN) row = NN - 1;
        float4 v = *reinterpret_cast<const float4*>(X + (size_t)row * FIN + c4 * 4);
        int mt = r >> 4, rr = r & 15, ks = c4 >> 1, hi = c4 & 1;
        int reg = ((rr >> 3) & 1) + 2 * hi;
        int lbase = (rr & 7) * 4;
        As[A_IDX(mt, ks, lbase + 0, reg)] = tf32r(v.x);
        As[A_IDX(mt, ks, lbase + 1, reg)] = tf32r(v.y);
        As[A_IDX(mt, ks, lbase + 2, reg)] = tf32r(v.z);
        As[A_IDX(mt, ks, lbase + 3, reg)] = tf32r(v.w);
    }
    // ---- B copy: 128 rows x 32 float4 (already tf32-rounded in g_b) ----
    // fragment (B): lane = groupID*4 + tid_g; groupID = n&7, tid_g = k&3; reg = (kwithin8>=4)
#pragma unroll
    for (int it = 0; it < 16; it++) {
        int i = tid + it * 256;
        int nl = i >> 5, c4 = i & 31;
        float4 v = *reinterpret_cast<const float4*>(g_b + (size_t)(bn + nl) * FIN + c4 * 4);
        int nt = nl >> 3, g = nl & 7, ks = c4 >> 1, hi = c4 & 1;
        int lbase = g * 4;
        Bs[B_IDX(nt, ks, lbase + 0, hi)] = v.x;
        Bs[B_IDX(nt, ks, lbase + 1, hi)] = v.y;
        Bs[B_IDX(nt, ks, lbase + 2, hi)] = v.z;
        Bs[B_IDX(nt, ks, lbase + 3, hi)] = v.w;
    }
    __syncthreads();

    // ---- mainloop: warp (wm 0..1, wn 0..3) computes 32x32 ----
    const int wm = wid >> 2, wn = wid & 3;
    float d[2][4][4];
#pragma unroll
    for (int mf = 0; mf < 2; mf++)
#pragma unroll
        for (int nf = 0; nf < 4; nf++)
#pragma unroll
            for (int q = 0; q < 4; q++) d[mf][nf][q] = 0.f;

#pragma unroll
    for (int ks = 0; ks < 16; ks++) {
        float4 a[2];
        float2 b[4];
#pragma unroll
        for (int mf = 0; mf < 2; mf++)
            a[mf] = *reinterpret_cast<const float4*>(&As[A_IDX(wm * 2 + mf, ks, lane, 0)]);
#pragma unroll
        for (int nf = 0; nf < 4; nf++)
            b[nf] = *reinterpret_cast<const float2*>(&Bs[B_IDX(wn * 4 + nf, ks, lane, 0)]);
#pragma unroll
        for (int mf = 0; mf < 2; mf++)
#pragma unroll
            for (int nf = 0; nf < 4; nf++)
                mma8(d[mf][nf], a[mf], b[nf]);
    }

    // ---- epilogue: d frag rows {g, g+8}, cols {2t, 2t+1} ----
    const int g = lane >> 2, t = lane & 3;
#pragma unroll
    for (int mf = 0; mf < 2; mf++) {
        int row0 = bm + wm * 32 + mf * 16 + g;
#pragma unroll
        for (int nf = 0; nf < 4; nf++) {
            int col = bn + wn * 32 + nf * 8 + 2 * t;
            store_pair(row0,     col, d[mf][nf][0], d[mf][nf][1]);
            store_pair(row0 + 8, col, d[mf][nf][2], d[mf][nf][3]);
        }
    }
}

// ---------------- CSR build ----------------
__global__ void zero_kernel() {
    int i = blockIdx.x * blockDim.x + threadIdx.x;
    if (i < NN) g_deg[i] = 0;
}

__global__ void count_kernel(const int* __restrict__ ei) {
    int e = blockIdx.x * blockDim.x + threadIdx.x;
    if (e >= EE) return;
    int d = clamp_idx(ei[EE + e]);
    atomicAdd(&g_deg[d], 1);
}

__global__ void scan_kernel() {
    __shared__ int sums[1024];
    const int t = threadIdx.x;
    const int CH = (NN + 1023) / 1024;
    int b = t * CH;
    int e = b + CH; if (e > NN) e = NN;
    if (b > NN) b = NN;
    int s = 0;
    for (int i = b; i < e; i++) s += g_deg[i];
    sums[t] = s;
    __syncthreads();
    for (int off = 1; off < 1024; off <<= 1) {
        int v = (t >= off) ? sums[t - off] : 0;
        __syncthreads();
        sums[t] += v;
        __syncthreads();
    }
    int run = sums[t] - s;
    for (int i = b; i < e; i++) {
        g_rowoff[i] = run;
        g_cursor[i] = run;
        run += g_deg[i];
    }
    if (t == 1023) g_rowoff[NN] = run;
}

__global__ void fill_kernel(const int* __restrict__ ei) {
    int e = blockIdx.x * blockDim.x + threadIdx.x;
    if (e >= EE) return;
    int s = clamp_idx(ei[e]);
    int d = clamp_idx(ei[EE + e]);
    int pos = atomicAdd(&g_cursor[d], 1);
    if (pos < EE) g_csrc[pos] = s;
}

// ---------------- fused per-dst node kernel (warp per node, single pass) ----------------
__device__ __forceinline__ float lrelu(float x) { return x > 0.f ? x : 0.2f * x; }

__device__ __forceinline__ void accum16(float acc[16], const float* __restrict__ base, float w) {
    const float4* p = reinterpret_cast<const float4*>(base);
    float4 v0 = p[0], v1 = p[1], v2 = p[2], v3 = p[3];
    acc[0]  = fmaf(w, v0.x, acc[0]);  acc[1]  = fmaf(w, v0.y, acc[1]);
    acc[2]  = fmaf(w, v0.z, acc[2]);  acc[3]  = fmaf(w, v0.w, acc[3]);
    acc[4]  = fmaf(w, v1.x, acc[4]);  acc[5]  = fmaf(w, v1.y, acc[5]);
    acc[6]  = fmaf(w, v1.z, acc[6]);  acc[7]  = fmaf(w, v1.w, acc[7]);
    acc[8]  = fmaf(w, v2.x, acc[8]);  acc[9]  = fmaf(w, v2.y, acc[9]);
    acc[10] = fmaf(w, v2.z, acc[10]); acc[11] = fmaf(w, v2.w, acc[11]);
    acc[12] = fmaf(w, v3.x, acc[12]); acc[13] = fmaf(w, v3.y, acc[13]);
    acc[14] = fmaf(w, v3.z, acc[14]); acc[15] = fmaf(w, v3.w, acc[15]);
}

__global__ void node_kernel(const float* __restrict__ bias, float* __restrict__ out) {
    int gw = (blockIdx.x * blockDim.x + threadIdx.x) >> 5;
    if (gw >= NN) return;
    const int n = gw;
    const int lane = threadIdx.x & 31;
    const bool l0 = (lane == 0);

    const int beg = g_rowoff[n];
    const int end = g_rowoff[n + 1];

    const float ad0 = g_adst[n * NH + lane];
    const float as0 = g_asrc[n * NH + lane];
    float ad1 = 0.f, as1 = 0.f;
    if (l0) { ad1 = g_adst[n * NH + 32]; as1 = g_asrc[n * NH + 32]; }

    float acc0[16], acc1[16];
#pragma unroll
    for (int c = 0; c < 16; c++) { acc0[c] = 0.f; acc1[c] = 0.f; }

    float den0 = __expf(lrelu(as0 + ad0));
    accum16(acc0, &g_h[(size_t)n * HC + lane * NC], den0);
    float den1 = 0.f;
    if (l0) {
        den1 = __expf(lrelu(as1 + ad1));
        accum16(acc1, &g_h[(size_t)n * HC + 32 * NC], den1);
    }

    for (int i = beg; i < end; i++) {
        int s = g_csrc[i];
        float w0 = __expf(lrelu(g_asrc[s * NH + lane] + ad0));
        den0 += w0;
        accum16(acc0, &g_h[(size_t)s * HC + lane * NC], w0);
        if (l0) {
            float w1 = __expf(lrelu(g_asrc[s * NH + 32] + ad1));
            den1 += w1;
            accum16(acc1, &g_h[(size_t)s * HC + 32 * NC], w1);
        }
    }

    const float inv0 = 1.f / den0;
    const float inv1 = l0 ? (1.f / den1) : 0.f;
#pragma unroll
    for (int c = 0; c < 16; c++) acc0[c] = acc0[c] * inv0 + acc1[c] * inv1;

    float res = 0.f;
#pragma unroll
    for (int c = 0; c < 16; c++) {
        float r = acc0[c];
        r += __shfl_xor_sync(0xffffffffu, r, 16);
        r += __shfl_xor_sync(0xffffffffu, r, 8);
        r += __shfl_xor_sync(0xffffffffu, r, 4);
        r += __shfl_xor_sync(0xffffffffu, r, 2);
        r += __shfl_xor_sync(0xffffffffu, r, 1);
        if (lane == c) res = r;
    }
    if (lane < 16)
        out[n * NC + lane] = tanhf(res * (1.f / 33.f) + bias[lane]);
}

// ---------------- launch ----------------
extern "C" void kernel_launch(void* const* d_in, const int* in_sizes, int n_in,
                              void* d_out, int out_size) {
    const float* x     = (const float*)d_in[0];
    const int*   ei    = (const int*)d_in[1];   // edge_index materializes as int32
    const float* W     = (const float*)d_in[2];
    const float* att_s = (const float*)d_in[3];
    const float* att_d = (const float*)d_in[4];
    const float* bias  = (const float*)d_in[5];
    float*       out   = (float*)d_out;

    static bool attr_set = false;  // idempotent attribute set (not a memory op)
    if (!attr_set) {
        cudaFuncSetAttribute(gemm_kernel, cudaFuncAttributeMaxDynamicSharedMemorySize, SMEM_GEMM);
        attr_set = true;
    }

    // CSR build
    zero_kernel<<<(NN + 255) / 256, 256>>>();
    count_kernel<<<(EE + 255) / 256, 256>>>(ei);
    scan_kernel<<<1, 1024>>>();
    fill_kernel<<<(EE + 255) / 256, 256>>>(ei);

    // fused B prep + tensor-core GEMM producing h, a_src, a_dst
    bprep_kernel<<<(NB * FIN + 255) / 256, 256>>>(W, att_s, att_d);
    dim3 gg(NTILES, MTILES);
    gemm_kernel<<<gg, 256, SMEM_GEMM>>>(x);

    // fused softmax-aggregate-mean-tanh
    node_kernel<<<(NN * 32 + 255) / 256, 256>>>(bias, out);
}

// round 7
// speedup vs baseline: 2.2156x; 1.2697x over previous
#include <cuda_runtime.h>
#include <math.h>
#include <stdint.h>

// Problem constants
#define NN 50000
#define EE 320000
#define FIN 128
#define NH 33
#define NC 16
#define HC 528     // NH*NC
#define NB 640     // padded B columns: 528 h | 33 a_src | 33 a_dst | pad

// GEMM tiling (legacy mma.sync m16n8k8 tf32)
#define BM 64
#define BN 128
#define MTILES ((NN + BM - 1) / BM)   // 782
#define NTILES (NB / BN)              // 5

// fragment-packed smem indices (floats); padded slot strides:
//   A slot = 132 floats (128 data + 4 pad), 16B-aligned stride
//   B slot = 66 floats (64 data + 2 pad)
#define A_IDX(mt, ks, lane, reg) (((mt)*16 + (ks))*132 + (lane)*4 + (reg))
#define B_IDX(nt, ks, lane, reg) (((nt)*16 + (ks))*66 + (lane)*2 + (reg))
#define A_FLOATS (64*132)             // 8448
#define B_FLOATS (256*66)             // 16896
#define SMEM_GEMM ((A_FLOATS + B_FLOATS) * 4)  // 101376 bytes

// ---------------- device scratch ----------------
__device__ __align__(16) float g_h[(size_t)NN * HC];
__device__ float g_asrc[NN * NH];
__device__ float g_adst[NN * NH];
__device__ __align__(16) float g_b[NB * FIN];  // fused B matrix, [640][128] n-major
__device__ int g_rowoff[NN + 1];
__device__ int g_cursor[NN];
__device__ int g_deg[NN];
__device__ int g_csrc[EE];

__device__ __forceinline__ int clamp_idx(int v) {
    return ((unsigned)v >= (unsigned)NN) ? 0 : v;
}

__device__ __forceinline__ float tf32r(float f) {
    uint32_t o;
    asm("cvt.rna.tf32.f32 %0, %1;" : "=r"(o) : "f"(f));
    return __uint_as_float(o);
}

// ---------------- B prep: B = [W^T | (W@att_src per head)^T | (W@att_dst)^T | 0] ----------------
__global__ void bprep_kernel(const float* __restrict__ W,
                             const float* __restrict__ attS, const float* __restrict__ attD) {
    int i = blockIdx.x * blockDim.x + threadIdx.x;   // i = k*640 + n
    if (i >= NB * FIN) return;
    int k = i / NB, n = i % NB;
    float v = 0.f;
    if (n < HC) {
        v = W[k * HC + n];
    } else if (n < HC + NH) {
        int h = n - HC;
        const float* wp = &W[k * HC + h * NC];
        const float* ap = &attS[h * NC];
#pragma unroll
        for (int c = 0; c < NC; c++) v = fmaf(wp[c], ap[c], v);
    } else if (n < HC + 2 * NH) {
        int h = n - HC - NH;
        const float* wp = &W[k * HC + h * NC];
        const float* ap = &attD[h * NC];
#pragma unroll
        for (int c = 0; c < NC; c++) v = fmaf(wp[c], ap[c], v);
    }
    g_b[(size_t)n * FIN + k] = tf32r(v);
}

// ---------------- tensor-core GEMM (mma.sync tf32), everything fused ----------------
__device__ __forceinline__ void mma8(float d[4], const float4& A, const float2& B) {
    asm volatile(
        "mma.sync.aligned.m16n8k8.row.col.f32.tf32.tf32.f32 "
        "{%0,%1,%2,%3}, {%4,%5,%6,%7}, {%8,%9}, {%0,%1,%2,%3};"
        : "+f"(d[0]), "+f"(d[1]), "+f"(d[2]), "+f"(d[3])
        : "r"(__float_as_uint(A.x)), "r"(__float_as_uint(A.y)),
          "r"(__float_as_uint(A.z)), "r"(__float_as_uint(A.w)),
          "r"(__float_as_uint(B.x)), "r"(__float_as_uint(B.y)));
}

__device__ __forceinline__ void store_one(int row, int col, float v) {
    if (col < HC) g_h[(size_t)row * HC + col] = v;
    else if (col < HC + NH) g_asrc[row * NH + (col - HC)] = v;
    else if (col < HC + 2 * NH) g_adst[row * NH + (col - HC - NH)] = v;
}

__device__ __forceinline__ void store_pair(int row, int col, float v0, float v1) {
    if (row >= NN) return;
    if (col + 1 < HC) {
        *reinterpret_cast<float2*>(&g_h[(size_t)row * HC + col]) = make_float2(v0, v1);
    } else {
        store_one(row, col, v0);
        store_one(row, col + 1, v1);
    }
}

// one block per M-tile; A staged once, loop over 5 N-tiles
__global__ void __launch_bounds__(256, 2)
gemm_kernel(const float* __restrict__ X) {
    extern __shared__ float sm[];
    float* As = sm;
    float* Bs = sm + A_FLOATS;

    const int tid = threadIdx.x;
    const int wid = tid >> 5;
    const int lane = tid & 31;
    const int bm = blockIdx.x * BM;

    // ---- A copy: 64 rows x 32 float4, fragment-packed, ONCE ----
    // fragment (m16n8k8 tf32 A): lane = (row&7)*4 + (k&3); reg = (row>=8) + 2*(kwithin8>=4)
#pragma unroll
    for (int it = 0; it < 8; it++) {
        int i = tid + it * 256;
        int r = i >> 5, c4 = i & 31;
        int row = bm + r; if (row >= NN) row = NN - 1;
        float4 v = *reinterpret_cast<const float4*>(X + (size_t)row * FIN + c4 * 4);
        int mt = r >> 4, rr = r & 15, ks = c4 >> 1, hi = c4 & 1;
        int reg = ((rr >> 3) & 1) + 2 * hi;
        int lbase = (rr & 7) * 4;
        As[A_IDX(mt, ks, lbase + 0, reg)] = tf32r(v.x);
        As[A_IDX(mt, ks, lbase + 1, reg)] = tf32r(v.y);
        As[A_IDX(mt, ks, lbase + 2, reg)] = tf32r(v.z);
        As[A_IDX(mt, ks, lbase + 3, reg)] = tf32r(v.w);
    }

    const int wm = wid >> 2, wn = wid & 3;
    const int g = lane >> 2, t = lane & 3;

    for (int nt5 = 0; nt5 < NTILES; nt5++) {
        const int bn = nt5 * BN;
        __syncthreads();   // As ready (iter 0); Bs free of prior readers (iters 1+)

        // ---- B copy: 128 rows x 32 float4 (already tf32-rounded) ----
        // fragment (B): lane = (n&7)*4 + (k&3); reg = (kwithin8>=4)
#pragma unroll
        for (int it = 0; it < 16; it++) {
            int i = tid + it * 256;
            int nl = i >> 5, c4 = i & 31;
            float4 v = *reinterpret_cast<const float4*>(g_b + (size_t)(bn + nl) * FIN + c4 * 4);
            int nt = nl >> 3, gg = nl & 7, ks = c4 >> 1, hi = c4 & 1;
            int lbase = gg * 4;
            Bs[B_IDX(nt, ks, lbase + 0, hi)] = v.x;
            Bs[B_IDX(nt, ks, lbase + 1, hi)] = v.y;
            Bs[B_IDX(nt, ks, lbase + 2, hi)] = v.z;
            Bs[B_IDX(nt, ks, lbase + 3, hi)] = v.w;
        }
        __syncthreads();

        // ---- mainloop: warp (wm 0..1, wn 0..3) computes 32x32 ----
        float d[2][4][4];
#pragma unroll
        for (int mf = 0; mf < 2; mf++)
#pragma unroll
            for (int nf = 0; nf < 4; nf++)
#pragma unroll
                for (int q = 0; q < 4; q++) d[mf][nf][q] = 0.f;

#pragma unroll
        for (int ks = 0; ks < 16; ks++) {
            float4 a[2];
            float2 b[4];
#pragma unroll
            for (int mf = 0; mf < 2; mf++)
                a[mf] = *reinterpret_cast<const float4*>(&As[A_IDX(wm * 2 + mf, ks, lane, 0)]);
#pragma unroll
            for (int nf = 0; nf < 4; nf++)
                b[nf] = *reinterpret_cast<const float2*>(&Bs[B_IDX(wn * 4 + nf, ks, lane, 0)]);
#pragma unroll
            for (int mf = 0; mf < 2; mf++)
#pragma unroll
                for (int nf = 0; nf < 4; nf++)
                    mma8(d[mf][nf], a[mf], b[nf]);
        }

        // ---- epilogue: d frag rows {g, g+8}, cols {2t, 2t+1} ----
#pragma unroll
        for (int mf = 0; mf < 2; mf++) {
            int row0 = bm + wm * 32 + mf * 16 + g;
#pragma unroll
            for (int nf = 0; nf < 4; nf++) {
                int col = bn + wn * 32 + nf * 8 + 2 * t;
                store_pair(row0,     col, d[mf][nf][0], d[mf][nf][1]);
                store_pair(row0 + 8, col, d[mf][nf][2], d[mf][nf][3]);
            }
        }
    }
}

// ---------------- CSR build ----------------
__global__ void zero_kernel() {
    int i = blockIdx.x * blockDim.x + threadIdx.x;
    if (i < NN) g_deg[i] = 0;
}

__global__ void count_kernel(const int* __restrict__ ei) {
    int e = blockIdx.x * blockDim.x + threadIdx.x;
    if (e >= EE) return;
    int d = clamp_idx(ei[EE + e]);
    atomicAdd(&g_deg[d], 1);
}

__global__ void scan_kernel() {
    __shared__ int sums[1024];
    const int t = threadIdx.x;
    const int CH = (NN + 1023) / 1024;
    int b = t * CH;
    int e = b + CH; if (e > NN) e = NN;
    if (b > NN) b = NN;
    int s = 0;
    for (int i = b; i < e; i++) s += g_deg[i];
    sums[t] = s;
    __syncthreads();
    for (int off = 1; off < 1024; off <<= 1) {
        int v = (t >= off) ? sums[t - off] : 0;
        __syncthreads();
        sums[t] += v;
        __syncthreads();
    }
    int run = sums[t] - s;
    for (int i = b; i < e; i++) {
        g_rowoff[i] = run;
        g_cursor[i] = run;
        run += g_deg[i];
    }
    if (t == 1023) g_rowoff[NN] = run;
}

__global__ void fill_kernel(const int* __restrict__ ei) {
    int e = blockIdx.x * blockDim.x + threadIdx.x;
    if (e >= EE) return;
    int s = clamp_idx(ei[e]);
    int d = clamp_idx(ei[EE + e]);
    int pos = atomicAdd(&g_cursor[d], 1);
    if (pos < EE) g_csrc[pos] = s;
}

// ---------------- fused per-dst node kernel (warp per node, single pass) ----------------
__device__ __forceinline__ float lrelu(float x) { return x > 0.f ? x : 0.2f * x; }

__device__ __forceinline__ void accum16(float acc[16], const float* __restrict__ base, float w) {
    const float4* p = reinterpret_cast<const float4*>(base);
    float4 v0 = p[0], v1 = p[1], v2 = p[2], v3 = p[3];
    acc[0]  = fmaf(w, v0.x, acc[0]);  acc[1]  = fmaf(w, v0.y, acc[1]);
    acc[2]  = fmaf(w, v0.z, acc[2]);  acc[3]  = fmaf(w, v0.w, acc[3]);
    acc[4]  = fmaf(w, v1.x, acc[4]);  acc[5]  = fmaf(w, v1.y, acc[5]);
    acc[6]  = fmaf(w, v1.z, acc[6]);  acc[7]  = fmaf(w, v1.w, acc[7]);
    acc[8]  = fmaf(w, v2.x, acc[8]);  acc[9]  = fmaf(w, v2.y, acc[9]);
    acc[10] = fmaf(w, v2.z, acc[10]); acc[11] = fmaf(w, v2.w, acc[11]);
    acc[12] = fmaf(w, v3.x, acc[12]); acc[13] = fmaf(w, v3.y, acc[13]);
    acc[14] = fmaf(w, v3.z, acc[14]); acc[15] = fmaf(w, v3.w, acc[15]);
}

__global__ void node_kernel(const float* __restrict__ bias, float* __restrict__ out) {
    int gw = (blockIdx.x * blockDim.x + threadIdx.x) >> 5;
    if (gw >= NN) return;
    const int n = gw;
    const int lane = threadIdx.x & 31;
    const bool l0 = (lane == 0);

    const int beg = g_rowoff[n];
    const int end = g_rowoff[n + 1];

    const float ad0 = g_adst[n * NH + lane];
    const float as0 = g_asrc[n * NH + lane];
    float ad1 = 0.f, as1 = 0.f;
    if (l0) { ad1 = g_adst[n * NH + 32]; as1 = g_asrc[n * NH + 32]; }

    float acc0[16], acc1[16];
#pragma unroll
    for (int c = 0; c < 16; c++) { acc0[c] = 0.f; acc1[c] = 0.f; }

    float den0 = __expf(lrelu(as0 + ad0));
    accum16(acc0, &g_h[(size_t)n * HC + lane * NC], den0);
    float den1 = 0.f;
    if (l0) {
        den1 = __expf(lrelu(as1 + ad1));
        accum16(acc1, &g_h[(size_t)n * HC + 32 * NC], den1);
    }

    // edge loop, unrolled x2 for memory-level parallelism
    int i = beg;
    for (; i + 2 <= end; i += 2) {
        int s0 = g_csrc[i];
        int s1 = g_csrc[i + 1];
        float w00 = __expf(lrelu(g_asrc[s0 * NH + lane] + ad0));
        float w01 = __expf(lrelu(g_asrc[s1 * NH + lane] + ad0));
        den0 += w00 + w01;
        accum16(acc0, &g_h[(size_t)s0 * HC + lane * NC], w00);
        accum16(acc0, &g_h[(size_t)s1 * HC + lane * NC], w01);
        if (l0) {
            float w10 = __expf(lrelu(g_asrc[s0 * NH + 32] + ad1));
            float w11 = __expf(lrelu(g_asrc[s1 * NH + 32] + ad1));
            den1 += w10 + w11;
            accum16(acc1, &g_h[(size_t)s0 * HC + 32 * NC], w10);
            accum16(acc1, &g_h[(size_t)s1 * HC + 32 * NC], w11);
        }
    }
    if (i < end) {
        int s = g_csrc[i];
        float w0 = __expf(lrelu(g_asrc[s * NH + lane] + ad0));
        den0 += w0;
        accum16(acc0, &g_h[(size_t)s * HC + lane * NC], w0);
        if (l0) {
            float w1 = __expf(lrelu(g_asrc[s * NH + 32] + ad1));
            den1 += w1;
            accum16(acc1, &g_h[(size_t)s * HC + 32 * NC], w1);
        }
    }

    const float inv0 = 1.f / den0;
    const float inv1 = l0 ? (1.f / den1) : 0.f;
#pragma unroll
    for (int c = 0; c < 16; c++) acc0[c] = acc0[c] * inv0 + acc1[c] * inv1;

    float res = 0.f;
#pragma unroll
    for (int c = 0; c < 16; c++) {
        float r = acc0[c];
        r += __shfl_xor_sync(0xffffffffu, r, 16);
        r += __shfl_xor_sync(0xffffffffu, r, 8);
        r += __shfl_xor_sync(0xffffffffu, r, 4);
        r += __shfl_xor_sync(0xffffffffu, r, 2);
        r += __shfl_xor_sync(0xffffffffu, r, 1);
        if (lane == c) res = r;
    }
    if (lane < 16)
        out[n * NC + lane] = tanhf(res * (1.f / 33.f) + bias[lane]);
}

// ---------------- launch ----------------
extern "C" void kernel_launch(void* const* d_in, const int* in_sizes, int n_in,
                              void* d_out, int out_size) {
    const float* x     = (const float*)d_in[0];
    const int*   ei    = (const int*)d_in[1];   // edge_index materializes as int32
    const float* W     = (const float*)d_in[2];
    const float* att_s = (const float*)d_in[3];
    const float* att_d = (const float*)d_in[4];
    const float* bias  = (const float*)d_in[5];
    float*       out   = (float*)d_out;

    static cudaStream_t s2 = nullptr;
    static cudaEvent_t evFork = nullptr, evJoin = nullptr;
    if (s2 == nullptr) {   // one-time resource setup (no device memory)
        cudaFuncSetAttribute(gemm_kernel, cudaFuncAttributeMaxDynamicSharedMemorySize, SMEM_GEMM);
        cudaStreamCreateWithFlags(&s2, cudaStreamNonBlocking);
        cudaEventCreateWithFlags(&evFork, cudaEventDisableTiming);
        cudaEventCreateWithFlags(&evJoin, cudaEventDisableTiming);
    }

    // fork: CSR build on s2, concurrent with bprep+GEMM on the main stream
    cudaEventRecord(evFork, 0);
    cudaStreamWaitEvent(s2, evFork, 0);
    zero_kernel<<<(NN + 255) / 256, 256, 0, s2>>>();
    count_kernel<<<(EE + 255) / 256, 256, 0, s2>>>(ei);
    scan_kernel<<<1, 1024, 0, s2>>>();
    fill_kernel<<<(EE + 255) / 256, 256, 0, s2>>>(ei);
    cudaEventRecord(evJoin, s2);

    // fused B prep + tensor-core GEMM producing h, a_src, a_dst (main stream)
    bprep_kernel<<<(NB * FIN + 255) / 256, 256>>>(W, att_s, att_d);
    gemm_kernel<<<MTILES, 256, SMEM_GEMM>>>(x);

    // join, then fused softmax-aggregate-mean-tanh
    cudaStreamWaitEvent(0, evJoin, 0);
    node_kernel<<<(NN * 32 + 255) / 256, 256>>>(bias, out);
}

// round 8
// speedup vs baseline: 3.1060x; 1.4019x over previous
#include <cuda_runtime.h>
#include <cuda_fp16.h>
#include <math.h>
#include <stdint.h>

// Problem constants
#define NN 50000
#define EE 320000
#define FIN 128
#define NH 33
#define NC 16
#define HC 528     // NH*NC
#define NB 640     // padded B columns: 528 h | 33 a_src | 33 a_dst | pad

// GEMM tiling (legacy mma.sync m16n8k8 tf32)
#define BM 64
#define BN 128
#define MTILES ((NN + BM - 1) / BM)   // 782
#define NTILES (NB / BN)              // 5

// fragment-packed smem indices (floats); padded slot strides:
//   A slot = 132 floats (128 data + 4 pad), B slot = 66 floats (64 data + 2 pad)
#define A_IDX(mt, ks, lane, reg) (((mt)*16 + (ks))*132 + (lane)*4 + (reg))
#define B_IDX(nt, ks, lane, reg) (((nt)*16 + (ks))*66 + (lane)*2 + (reg))
#define A_FLOATS (64*132)             // 8448
#define B_FLOATS (256*66)             // 16896
#define SMEM_GEMM ((A_FLOATS + B_FLOATS) * 4)  // 101376 bytes

// ---------------- device scratch ----------------
__device__ __align__(16) __half g_hh[(size_t)NN * HC];  // h in fp16 (~52.8 MB)
__device__ float g_asrc[NN * NH];
__device__ float g_adst[NN * NH];
__device__ __align__(16) float g_b[NB * FIN];  // fused B matrix, [640][128] n-major
__device__ int g_rowoff[NN + 1];
__device__ int g_cursor[NN];
__device__ int g_deg[NN];
__device__ int g_csrc[EE];

__device__ __forceinline__ int clamp_idx(int v) {
    return ((unsigned)v >= (unsigned)NN) ? 0 : v;
}

__device__ __forceinline__ float tf32r(float f) {
    uint32_t o;
    asm("cvt.rna.tf32.f32 %0, %1;" : "=r"(o) : "f"(f));
    return __uint_as_float(o);
}

// ---------------- B prep: B = [W^T | (W@att_src per head)^T | (W@att_dst)^T | 0] ----------------
__global__ void bprep_kernel(const float* __restrict__ W,
                             const float* __restrict__ attS, const float* __restrict__ attD) {
    int i = blockIdx.x * blockDim.x + threadIdx.x;   // i = k*640 + n
    if (i >= NB * FIN) return;
    int k = i / NB, n = i % NB;
    float v = 0.f;
    if (n < HC) {
        v = W[k * HC + n];
    } else if (n < HC + NH) {
        int h = n - HC;
        const float* wp = &W[k * HC + h * NC];
        const float* ap = &attS[h * NC];
#pragma unroll
        for (int c = 0; c < NC; c++) v = fmaf(wp[c], ap[c], v);
    } else if (n < HC + 2 * NH) {
        int h = n - HC - NH;
        const float* wp = &W[k * HC + h * NC];
        const float* ap = &attD[h * NC];
#pragma unroll
        for (int c = 0; c < NC; c++) v = fmaf(wp[c], ap[c], v);
    }
    g_b[(size_t)n * FIN + k] = tf32r(v);
}

// ---------------- tensor-core GEMM (mma.sync tf32), everything fused ----------------
__device__ __forceinline__ void mma8(float d[4], const float4& A, const float2& B) {
    asm volatile(
        "mma.sync.aligned.m16n8k8.row.col.f32.tf32.tf32.f32 "
        "{%0,%1,%2,%3}, {%4,%5,%6,%7}, {%8,%9}, {%0,%1,%2,%3};"
        : "+f"(d[0]), "+f"(d[1]), "+f"(d[2]), "+f"(d[3])
        : "r"(__float_as_uint(A.x)), "r"(__float_as_uint(A.y)),
          "r"(__float_as_uint(A.z)), "r"(__float_as_uint(A.w)),
          "r"(__float_as_uint(B.x)), "r"(__float_as_uint(B.y)));
}

__device__ __forceinline__ void store_att(int row, int col, float v) {
    if (col < HC + NH) g_asrc[row * NH + (col - HC)] = v;
    else if (col < HC + 2 * NH) g_adst[row * NH + (col - HC - NH)] = v;
}

__device__ __forceinline__ void store_pair(int row, int col, float v0, float v1) {
    if (row >= NN) return;
    if (col < HC) {   // h cols come in even-aligned pairs (col = ...+2t)
        *reinterpret_cast<__half2*>(&g_hh[(size_t)row * HC + col]) = __floats2half2_rn(v0, v1);
    } else {
        store_att(row, col, v0);
        store_att(row, col + 1, v1);
    }
}

// one block per M-tile; A staged once, loop over 5 N-tiles
__global__ void __launch_bounds__(256, 2)
gemm_kernel(const float* __restrict__ X) {
    extern __shared__ float sm[];
    float* As = sm;
    float* Bs = sm + A_FLOATS;

    const int tid = threadIdx.x;
    const int wid = tid >> 5;
    const int lane = tid & 31;
    const int bm = blockIdx.x * BM;

    // ---- A copy: 64 rows x 32 float4, fragment-packed, ONCE ----
    // fragment (m16n8k8 tf32 A): lane = (row&7)*4 + (k&3); reg = (row>=8) + 2*(kwithin8>=4)
#pragma unroll
    for (int it = 0; it < 8; it++) {
        int i = tid + it * 256;
        int r = i >> 5, c4 = i & 31;
        int row = bm + r; if (row >= NN) row = NN - 1;
        float4 v = *reinterpret_cast<const float4*>(X + (size_t)row * FIN + c4 * 4);
        int mt = r >> 4, rr = r & 15, ks = c4 >> 1, hi = c4 & 1;
        int reg = ((rr >> 3) & 1) + 2 * hi;
        int lbase = (rr & 7) * 4;
        As[A_IDX(mt, ks, lbase + 0, reg)] = tf32r(v.x);
        As[A_IDX(mt, ks, lbase + 1, reg)] = tf32r(v.y);
        As[A_IDX(mt, ks, lbase + 2, reg)] = tf32r(v.z);
        As[A_IDX(mt, ks, lbase + 3, reg)] = tf32r(v.w);
    }

    const int wm = wid >> 2, wn = wid & 3;
    const int g = lane >> 2, t = lane & 3;

    for (int nt5 = 0; nt5 < NTILES; nt5++) {
        const int bn = nt5 * BN;
        __syncthreads();   // As ready (iter 0); Bs free of prior readers (iters 1+)

        // ---- B copy: 128 rows x 32 float4 (already tf32-rounded) ----
#pragma unroll
        for (int it = 0; it < 16; it++) {
            int i = tid + it * 256;
            int nl = i >> 5, c4 = i & 31;
            float4 v = *reinterpret_cast<const float4*>(g_b + (size_t)(bn + nl) * FIN + c4 * 4);
            int nt = nl >> 3, gg = nl & 7, ks = c4 >> 1, hi = c4 & 1;
            int lbase = gg * 4;
            Bs[B_IDX(nt, ks, lbase + 0, hi)] = v.x;
            Bs[B_IDX(nt, ks, lbase + 1, hi)] = v.y;
            Bs[B_IDX(nt, ks, lbase + 2, hi)] = v.z;
            Bs[B_IDX(nt, ks, lbase + 3, hi)] = v.w;
        }
        __syncthreads();

        // ---- mainloop: warp (wm 0..1, wn 0..3) computes 32x32 ----
        float d[2][4][4];
#pragma unroll
        for (int mf = 0; mf < 2; mf++)
#pragma unroll
            for (int nf = 0; nf < 4; nf++)
#pragma unroll
                for (int q = 0; q < 4; q++) d[mf][nf][q] = 0.f;

#pragma unroll
        for (int ks = 0; ks < 16; ks++) {
            float4 a[2];
            float2 b[4];
#pragma unroll
            for (int mf = 0; mf < 2; mf++)
                a[mf] = *reinterpret_cast<const float4*>(&As[A_IDX(wm * 2 + mf, ks, lane, 0)]);
#pragma unroll
            for (int nf = 0; nf < 4; nf++)
                b[nf] = *reinterpret_cast<const float2*>(&Bs[B_IDX(wn * 4 + nf, ks, lane, 0)]);
#pragma unroll
            for (int mf = 0; mf < 2; mf++)
#pragma unroll
                for (int nf = 0; nf < 4; nf++)
                    mma8(d[mf][nf], a[mf], b[nf]);
        }

        // ---- epilogue: d frag rows {g, g+8}, cols {2t, 2t+1} ----
#pragma unroll
        for (int mf = 0; mf < 2; mf++) {
            int row0 = bm + wm * 32 + mf * 16 + g;
#pragma unroll
            for (int nf = 0; nf < 4; nf++) {
                int col = bn + wn * 32 + nf * 8 + 2 * t;
                store_pair(row0,     col, d[mf][nf][0], d[mf][nf][1]);
                store_pair(row0 + 8, col, d[mf][nf][2], d[mf][nf][3]);
            }
        }
    }
}

// ---------------- CSR build ----------------
__global__ void zero_kernel() {
    int i = blockIdx.x * blockDim.x + threadIdx.x;
    if (i < NN) g_deg[i] = 0;
}

__global__ void count_kernel(const int* __restrict__ ei) {
    int e = blockIdx.x * blockDim.x + threadIdx.x;
    if (e >= EE) return;
    int d = clamp_idx(ei[EE + e]);
    atomicAdd(&g_deg[d], 1);
}

__global__ void scan_kernel() {
    __shared__ int sums[1024];
    const int t = threadIdx.x;
    const int CH = (NN + 1023) / 1024;
    int b = t * CH;
    int e = b + CH; if (e > NN) e = NN;
    if (b > NN) b = NN;
    int s = 0;
    for (int i = b; i < e; i++) s += g_deg[i];
    sums[t] = s;
    __syncthreads();
    for (int off = 1; off < 1024; off <<= 1) {
        int v = (t >= off) ? sums[t - off] : 0;
        __syncthreads();
        sums[t] += v;
        __syncthreads();
    }
    int run = sums[t] - s;
    for (int i = b; i < e; i++) {
        g_rowoff[i] = run;
        g_cursor[i] = run;
        run += g_deg[i];
    }
    if (t == 1023) g_rowoff[NN] = run;
}

__global__ void fill_kernel(const int* __restrict__ ei) {
    int e = blockIdx.x * blockDim.x + threadIdx.x;
    if (e >= EE) return;
    int s = clamp_idx(ei[e]);
    int d = clamp_idx(ei[EE + e]);
    int pos = atomicAdd(&g_cursor[d], 1);
    if (pos < EE) g_csrc[pos] = s;
}

// ---------------- fused per-dst node kernel (warp per node, single pass, fp16 gather) ----
__device__ __forceinline__ float lrelu(float x) { return x > 0.f ? x : 0.2f * x; }

__device__ __forceinline__ void accum16h(float acc[16], const __half* __restrict__ base, float w) {
    const uint4* p = reinterpret_cast<const uint4*>(base);
    uint4 u0 = p[0], u1 = p[1];
    uint32_t us[8] = {u0.x, u0.y, u0.z, u0.w, u1.x, u1.y, u1.z, u1.w};
#pragma unroll
    for (int j = 0; j < 8; j++) {
        float2 f = __half22float2(*reinterpret_cast<const __half2*>(&us[j]));
        acc[2*j]     = fmaf(w, f.x, acc[2*j]);
        acc[2*j + 1] = fmaf(w, f.y, acc[2*j + 1]);
    }
}

__global__ void node_kernel(const float* __restrict__ bias, float* __restrict__ out) {
    int gw = (blockIdx.x * blockDim.x + threadIdx.x) >> 5;
    if (gw >= NN) return;
    const int n = gw;
    const int lane = threadIdx.x & 31;
    const bool l0 = (lane == 0);

    const int beg = g_rowoff[n];
    const int end = g_rowoff[n + 1];

    const float ad0 = g_adst[n * NH + lane];
    const float as0 = g_asrc[n * NH + lane];
    float ad1 = 0.f, as1 = 0.f;
    if (l0) { ad1 = g_adst[n * NH + 32]; as1 = g_asrc[n * NH + 32]; }

    float acc0[16], acc1[16];
#pragma unroll
    for (int c = 0; c < 16; c++) { acc0[c] = 0.f; acc1[c] = 0.f; }

    float den0 = __expf(lrelu(as0 + ad0));
    accum16h(acc0, &g_hh[(size_t)n * HC + lane * NC], den0);
    float den1 = 0.f;
    if (l0) {
        den1 = __expf(lrelu(as1 + ad1));
        accum16h(acc1, &g_hh[(size_t)n * HC + 32 * NC], den1);
    }

    // edge loop, unrolled x2 for memory-level parallelism
    int i = beg;
    for (; i + 2 <= end; i += 2) {
        int s0 = g_csrc[i];
        int s1 = g_csrc[i + 1];
        float w00 = __expf(lrelu(g_asrc[s0 * NH + lane] + ad0));
        float w01 = __expf(lrelu(g_asrc[s1 * NH + lane] + ad0));
        den0 += w00 + w01;
        accum16h(acc0, &g_hh[(size_t)s0 * HC + lane * NC], w00);
        accum16h(acc0, &g_hh[(size_t)s1 * HC + lane * NC], w01);
        if (l0) {
            float w10 = __expf(lrelu(g_asrc[s0 * NH + 32] + ad1));
            float w11 = __expf(lrelu(g_asrc[s1 * NH + 32] + ad1));
            den1 += w10 + w11;
            accum16h(acc1, &g_hh[(size_t)s0 * HC + 32 * NC], w10);
            accum16h(acc1, &g_hh[(size_t)s1 * HC + 32 * NC], w11);
        }
    }
    if (i < end) {
        int s = g_csrc[i];
        float w0 = __expf(lrelu(g_asrc[s * NH + lane] + ad0));
        den0 += w0;
        accum16h(acc0, &g_hh[(size_t)s * HC + lane * NC], w0);
        if (l0) {
            float w1 = __expf(lrelu(g_asrc[s * NH + 32] + ad1));
            den1 += w1;
            accum16h(acc1, &g_hh[(size_t)s * HC + 32 * NC], w1);
        }
    }

    const float inv0 = 1.f / den0;
    const float inv1 = l0 ? (1.f / den1) : 0.f;
#pragma unroll
    for (int c = 0; c < 16; c++) acc0[c] = acc0[c] * inv0 + acc1[c] * inv1;

    float res = 0.f;
#pragma unroll
    for (int c = 0; c < 16; c++) {
        float r = acc0[c];
        r += __shfl_xor_sync(0xffffffffu, r, 16);
        r += __shfl_xor_sync(0xffffffffu, r, 8);
        r += __shfl_xor_sync(0xffffffffu, r, 4);
        r += __shfl_xor_sync(0xffffffffu, r, 2);
        r += __shfl_xor_sync(0xffffffffu, r, 1);
        if (lane == c) res = r;
    }
    if (lane < 16)
        out[n * NC + lane] = tanhf(res * (1.f / 33.f) + bias[lane]);
}

// ---------------- launch ----------------
extern "C" void kernel_launch(void* const* d_in, const int* in_sizes, int n_in,
                              void* d_out, int out_size) {
    const float* x     = (const float*)d_in[0];
    const int*   ei    = (const int*)d_in[1];   // edge_index materializes as int32
    const float* W     = (const float*)d_in[2];
    const float* att_s = (const float*)d_in[3];
    const float* att_d = (const float*)d_in[4];
    const float* bias  = (const float*)d_in[5];
    float*       out   = (float*)d_out;

    static cudaStream_t s2 = nullptr;
    static cudaEvent_t evFork = nullptr, evJoin = nullptr;
    if (s2 == nullptr) {   // one-time resource setup (no device memory)
        cudaFuncSetAttribute(gemm_kernel, cudaFuncAttributeMaxDynamicSharedMemorySize, SMEM_GEMM);
        cudaStreamCreateWithFlags(&s2, cudaStreamNonBlocking);
        cudaEventCreateWithFlags(&evFork, cudaEventDisableTiming);
        cudaEventCreateWithFlags(&evJoin, cudaEventDisableTiming);
    }

    // fork: CSR build on s2, concurrent with bprep+GEMM on the main stream
    cudaEventRecord(evFork, 0);
    cudaStreamWaitEvent(s2, evFork, 0);
    zero_kernel<<<(NN + 255) / 256, 256, 0, s2>>>();
    count_kernel<<<(EE + 255) / 256, 256, 0, s2>>>(ei);
    scan_kernel<<<1, 1024, 0, s2>>>();
    fill_kernel<<<(EE + 255) / 256, 256, 0, s2>>>(ei);
    cudaEventRecord(evJoin, s2);

    // fused B prep + tensor-core GEMM producing h (fp16), a_src, a_dst (main stream)
    bprep_kernel<<<(NB * FIN + 255) / 256, 256>>>(W, att_s, att_d);
    gemm_kernel<<<MTILES, 256, SMEM_GEMM>>>(x);

    // join, then fused softmax-aggregate-mean-tanh
    cudaStreamWaitEvent(0, evJoin, 0);
    node_kernel<<<(NN * 32 + 255) / 256, 256>>>(bias, out);
}